// round 11
// baseline (speedup 1.0000x reference)
#include <cuda_runtime.h>

#define NTHR 512
#define TPG  16            // tokens per group
#define S    276           // staging row stride in floats (16*16 + 20 pad)

typedef unsigned long long ull;

// ---------------- shared memory layout (in floats) ----------------
#define WBT_SZ  (9*32*64)              // wbT[a][i][o], o contiguous
#define WOT_SZ  (9*32*32)              // woT[a][i][o]
#define XS_SZ   (32*S + 8)             // xs rows (aliased by gs in P3/P4)
#define HS_SZ   (64*S + 8)             // hs rows (aliased by out-staging)
#define WBT_OFF 0
#define WOT_OFF (WBT_OFF + WBT_SZ)
#define XS_OFF  (WOT_OFF + WOT_SZ)
#define HS_OFF  (XS_OFF + XS_SZ)
#define BB_OFF  (HS_OFF + HS_SZ)       // 64
#define BO_OFF  (BB_OFF + 64)          // 32
#define RW_OFF  (BO_OFF + 32)          // 16
#define F_TOTAL (RW_OFF + 16)
#define SMEM_BYTES (F_TOTAL * 4)

// component slot swizzle (bijective), bank-swizzled row offsets
__host__ __device__ constexpr int cslot(int k) { return k ^ (k >> 2); }
__host__ __device__ constexpr int rowX(int i)  { return XS_OFF + i * S + ((i >> 3) & 1) * 4; }
__host__ __device__ constexpr int rowH(int o)  { return HS_OFF + o * S + ((o >> 3) & 1) * 4; }

// ---------------- blade algebra ----------------
// blade order: 1,e0,e1,e2,e3,e01,e02,e03,e12,e13,e23,e012,e013,e023,e123,e0123
__constant__ int c_GRADE[16] = {0,1,1,1,1,2,2,2,2,2,2,3,3,3,3,4};
__constant__ int c_PART [16] = {-1,0,-1,-1,-1,2,3,4,-1,-1,-1,8,9,10,-1,14};
__constant__ int c_A2   [16] = {0,5,0,0,0,6,6,6,0,0,0,7,7,7,0,8};
// component pairs: warps 0-3 = e0-pairs (64 iters), 4-7 = non-e0 pairs (32 iters)
__constant__ int c_PAIR[8][2] = {{1,5},{6,7},{11,12},{13,15},
                                 {0,2},{3,4},{8,9},{10,14}};

// ---- compile-time Cayley tables ----
constexpr int MASKC[16]  = {0,1,2,4,8,3,5,9,6,10,12,7,11,13,14,15};
constexpr int IMASKC[16] = {0,1,2,5,3,6,8,11,4,7,9,12,10,13,14,15};
constexpr int popc4c(int x) { int v = 0; for (int b = 0; b < 4; b++) v += (x >> b) & 1; return v; }
constexpr int invcc(int A, int B) {
    int v = 0;
    for (int g = 0; g < 4; g++) if ((B >> g) & 1) v += popc4c(A >> (g + 1));
    return v;
}
struct CTerm { int i, j, s; };
struct CK    { CTerm t[16]; int n; };
struct CTabs { CK gp[16]; CK jc[16]; };
constexpr CTabs buildT() {
    CTabs T{};
    for (int i = 0; i < 16; i++)
        for (int j = 0; j < 16; j++) {
            int A = MASKC[i], B = MASKC[j];
            if (A & B & 1) continue;                    // e0*e0 = 0
            int s = (invcc(A, B) & 1) ? -1 : 1;
            int k = IMASKC[A ^ B];
            T.gp[k].t[T.gp[k].n].i = i;
            T.gp[k].t[T.gp[k].n].j = j;
            T.gp[k].t[T.gp[k].n].s = s;
            T.gp[k].n++;
        }
    int ds[16] = {};
    for (int i = 0; i < 16; i++) {
        int A = MASKC[i];
        ds[i] = (invcc(A, 15 ^ A) & 1) ? -1 : 1;
    }
    for (int i = 0; i < 16; i++)
        for (int j = 0; j < 16; j++) {
            int A = MASKC[i], B = MASKC[j];
            int da = 15 ^ A, db = 15 ^ B;
            if (da & db) continue;                      // wedge of duals vanishes
            int w  = (invcc(da, db) & 1) ? -1 : 1;
            int kk = IMASKC[A & B];
            int val = ds[i] * ds[j] * w * ds[kk];
            T.jc[kk].t[T.jc[kk].n].i = i;
            T.jc[kk].t[T.jc[kk].n].j = j;
            T.jc[kk].t[T.jc[kk].n].s = val;
            T.jc[kk].n++;
        }
    return T;
}
constexpr CTabs CT = buildT();

// ---- packed f32x2 helpers ----
__device__ __forceinline__ void fma2(ull& d, ull a, ull b) {
    asm("fma.rn.f32x2 %0, %1, %2, %0;" : "+l"(d) : "l"(a), "l"(b));
}
__device__ __forceinline__ ull pk2(float s) {
    ull d; asm("mov.b64 %0, {%1, %1};" : "=l"(d) : "f"(s)); return d;
}
__device__ __forceinline__ void add2(ull& d, ull a) {
    asm("add.rn.f32x2 %0, %0, %1;" : "+l"(d) : "l"(a));
}

// ---- P2 MAC block: 32 i-iters, o-quad x 16 tokens ----
__device__ __forceinline__ void mac32_t16(
    ull (&acc)[4][8], const float* __restrict__ w, int ws,
    const float* __restrict__ smb, int sl)
{
    #pragma unroll 8
    for (int i = 0; i < 32; i++) {
        float4 wv = *(const float4*)(w + i * ws);
        const float* xp = smb + rowX(i) + sl;
        ulonglong2 x0 = *(const ulonglong2*)(xp);
        ulonglong2 x1 = *(const ulonglong2*)(xp + 4);
        ulonglong2 x2 = *(const ulonglong2*)(xp + 8);
        ulonglong2 x3 = *(const ulonglong2*)(xp + 12);
        ull xv[8] = {x0.x, x0.y, x1.x, x1.y, x2.x, x2.y, x3.x, x3.y};
        ull w0 = pk2(wv.x), w1 = pk2(wv.y), w2 = pk2(wv.z), w3 = pk2(wv.w);
        #pragma unroll
        for (int p = 0; p < 8; p++) {
            fma2(acc[0][p], xv[p], w0); fma2(acc[1][p], xv[p], w1);
            fma2(acc[2][p], xv[p], w2); fma2(acc[3][p], xv[p], w3);
        }
    }
}

// ---- P4 MAC block: 32 i-iters, o-quad x 8 tokens ----
__device__ __forceinline__ void mac32_t8(
    ull (&acc)[4][4], const float* __restrict__ w, int ws,
    const float* __restrict__ smb, int sl)
{
    #pragma unroll 8
    for (int i = 0; i < 32; i++) {
        float4 wv = *(const float4*)(w + i * ws);
        const float* xp = smb + rowX(i) + sl;
        ulonglong2 x0 = *(const ulonglong2*)(xp);
        ulonglong2 x1 = *(const ulonglong2*)(xp + 4);
        ull xv[4] = {x0.x, x0.y, x1.x, x1.y};
        ull w0 = pk2(wv.x), w1 = pk2(wv.y), w2 = pk2(wv.z), w3 = pk2(wv.w);
        #pragma unroll
        for (int p = 0; p < 4; p++) {
            fma2(acc[0][p], xv[p], w0); fma2(acc[1][p], xv[p], w1);
            fma2(acc[2][p], xv[p], w2); fma2(acc[3][p], xv[p], w3);
        }
    }
}

// ---- P3: one component K, compile-time term list ----
template<int SIDE, int K>
__device__ __forceinline__ float bil_k(const float (&L)[16], const float (&R)[16]) {
    constexpr CK ck = SIDE ? CT.jc[K] : CT.gp[K];
    float acc = 0.f;
    #pragma unroll
    for (int e = 0; e < ck.n; e++) {
        float l = (ck.t[e].s < 0) ? -L[ck.t[e].i] : L[ck.t[e].i];
        acc = fmaf(l, R[ck.t[e].j], acc);
    }
    return acc;
}

template<int SIDE, int K>
__device__ __forceinline__ void bil_all(const float (&L)[16], const float (&R)[16],
                                        float* __restrict__ dst, float scale) {
    if constexpr (K < 16) {
        float v = bil_k<SIDE, K>(L, R);
        if constexpr (SIDE) v *= scale;
        dst[cslot(K) * 16] = v;
        bil_all<SIDE, K + 1>(L, R, dst, scale);
    }
}

__global__ __launch_bounds__(NTHR, 1)
void gatr_fused_kernel(
    const float* __restrict__ x, const float* __restrict__ ref,
    const float* __restrict__ w_bil, const float* __restrict__ b_bil,
    const float* __restrict__ w_out, const float* __restrict__ b_out,
    float* __restrict__ out, int ngroups)
{
    extern __shared__ float sm[];
    float* wbT = sm + WBT_OFF;
    float* woT = sm + WOT_OFF;
    float* bb  = sm + BB_OFF;
    float* bo  = sm + BO_OFF;
    float* rw  = sm + RW_OFF;

    const int tid = threadIdx.x;

    // ---- stage weights transposed ----
    for (int e = tid; e < 64 * 32 * 9; e += NTHR) {
        int o = e / 288, r = e % 288, i = r / 9, a = r % 9;
        wbT[(a * 32 + i) * 64 + o] = w_bil[e];
    }
    for (int e = tid; e < 32 * 32 * 9; e += NTHR) {
        int o = e / 288, r = e % 288, i = r / 9, a = r % 9;
        woT[(a * 32 + i) * 32 + o] = w_out[e];
    }
    if (tid < 64) bb[tid] = b_bil[tid];
    if (tid < 32) bo[tid] = b_out[tid];

    const int e_id = tid & 127;
    const int t0   = (tid >> 7) * 4;

    // ---- prefetch + stage first group ----
    float4 pf[4];
    float  prw = 0.f;
    {
        int g = blockIdx.x;
        size_t base = ((size_t)g * TPG + t0) * 512 + (size_t)e_id * 4;
        #pragma unroll
        for (int j = 0; j < 4; j++) pf[j] = *(const float4*)(x + base + (size_t)j * 512);
        if (tid < TPG) prw = ref[((size_t)g * TPG + tid) * 16 + 15];

        const float* p0 = (const float*)&pf[0];
        const float* p1 = (const float*)&pf[1];
        const float* p2 = (const float*)&pf[2];
        const float* p3 = (const float*)&pf[3];
        #pragma unroll
        for (int c = 0; c < 4; c++) {
            int k = (e_id & 3) * 4 + c;
            float* d = sm + rowX(e_id >> 2) + cslot(k) * 16 + t0;
            *(float4*)d = make_float4(p0[c], p1[c], p2[c], p3[c]);
        }
        if (tid < TPG) rw[tid] = prw;
    }

    const int w_id = tid >> 5, lane = tid & 31;

    for (int g = blockIdx.x; g < ngroups; g += gridDim.x) {
        __syncthreads();   // xs / rw ready

        // prefetch next group (LDG latency hidden under P2)
        int gn = g + gridDim.x;
        bool more = gn < ngroups;
        if (more) {
            size_t base = ((size_t)gn * TPG + t0) * 512 + (size_t)e_id * 4;
            #pragma unroll
            for (int j = 0; j < 4; j++) pf[j] = *(const float4*)(x + base + (size_t)j * 512);
            if (tid < TPG) prw = ref[((size_t)gn * TPG + tid) * 16 + 15];
        }

        // ---- P2: equi_linear #1 -> hs rows 0..63 (8 pair-warps, o-quad x 16 tok) ----
        if (w_id < 8) {
            int m = lane >> 4, q = lane & 15;
            int k  = c_PAIR[w_id][m];
            int o0 = 4 * q;
            int sl = cslot(k) * 16;
            ull acc[4][8];
            #pragma unroll
            for (int oo = 0; oo < 4; oo++)
                #pragma unroll
                for (int p = 0; p < 8; p++) acc[oo][p] = 0ull;

            mac32_t16(acc, wbT + (c_GRADE[k] * 32) * 64 + o0, 64, sm, sl);
            int pk = c_PART[k];                 // warp-uniform class (pairs same class)
            if (pk >= 0)
                mac32_t16(acc, wbT + (c_A2[k] * 32) * 64 + o0, 64, sm, cslot(pk) * 16);

            if (k == 0) {
                #pragma unroll
                for (int oo = 0; oo < 4; oo++) {
                    ull b = pk2(bb[o0 + oo]);
                    #pragma unroll
                    for (int p = 0; p < 8; p++) add2(acc[oo][p], b);
                }
            }
            #pragma unroll
            for (int oo = 0; oo < 4; oo++) {
                float* d = sm + rowH(o0 + oo) + sl;
                *(ulonglong2*)(d)      = make_ulonglong2(acc[oo][0], acc[oo][1]);
                *(ulonglong2*)(d + 4)  = make_ulonglong2(acc[oo][2], acc[oo][3]);
                *(ulonglong2*)(d + 8)  = make_ulonglong2(acc[oo][4], acc[oo][5]);
                *(ulonglong2*)(d + 12) = make_ulonglong2(acc[oo][6], acc[oo][7]);
            }
        }
        __syncthreads();

        // ---- P3: GP + join -> gs (xs region) rows 0..31 (512 threads) ----
        {
            int side = tid >> 8, c = (tid >> 4) & 15, t = tid & 15;
            const float* Lp = sm + rowH(side * 32 + c) + t;
            const float* Rp = sm + rowH(side * 32 + 16 + c) + t;
            float L[16], R[16];
            #pragma unroll
            for (int i = 0; i < 16; i++) {
                L[i] = Lp[cslot(i) * 16];
                R[i] = Rp[cslot(i) * 16];
            }
            float* dst = sm + rowX(side * 16 + c) + t;
            float scale = rw[t];
            if (side == 0) bil_all<0, 0>(L, R, dst, scale);
            else           bil_all<1, 0>(L, R, dst, scale);
        }
        __syncthreads();

        // ---- P4: equi_linear #2 -> staging in hs rows 0..31 (8 pair-warps) ----
        if (w_id < 8) {
            int m = lane >> 4, h = (lane >> 3) & 1, q = lane & 7;
            int k  = c_PAIR[w_id][m];
            int o0 = 4 * q;
            int sl = cslot(k) * 16 + h * 8;
            ull acc[4][4];
            #pragma unroll
            for (int oo = 0; oo < 4; oo++)
                #pragma unroll
                for (int p = 0; p < 4; p++) acc[oo][p] = 0ull;

            mac32_t8(acc, woT + (c_GRADE[k] * 32) * 32 + o0, 32, sm, sl);
            int pk = c_PART[k];
            if (pk >= 0)
                mac32_t8(acc, woT + (c_A2[k] * 32) * 32 + o0, 32, sm,
                         cslot(pk) * 16 + h * 8);

            if (k == 0) {
                #pragma unroll
                for (int oo = 0; oo < 4; oo++) {
                    ull b = pk2(bo[o0 + oo]);
                    #pragma unroll
                    for (int p = 0; p < 4; p++) add2(acc[oo][p], b);
                }
            }
            #pragma unroll
            for (int oo = 0; oo < 4; oo++) {
                float* d = sm + rowH(o0 + oo) + sl;
                *(ulonglong2*)(d)     = make_ulonglong2(acc[oo][0], acc[oo][1]);
                *(ulonglong2*)(d + 4) = make_ulonglong2(acc[oo][2], acc[oo][3]);
            }
        }
        __syncthreads();

        // ---- P5: coalesced store + stage next group's x ----
        {
            float4 sv[4];
            #pragma unroll
            for (int c = 0; c < 4; c++) {
                int k = (e_id & 3) * 4 + c;
                sv[c] = *(const float4*)(sm + rowH(e_id >> 2) + cslot(k) * 16 + t0);
            }
            size_t base = ((size_t)g * TPG + t0) * 512 + (size_t)e_id * 4;
            const float* s0 = (const float*)&sv[0];
            const float* s1 = (const float*)&sv[1];
            const float* s2 = (const float*)&sv[2];
            const float* s3 = (const float*)&sv[3];
            #pragma unroll
            for (int j = 0; j < 4; j++)
                *(float4*)(out + base + (size_t)j * 512) =
                    make_float4(s0[j], s1[j], s2[j], s3[j]);

            if (more) {
                const float* p0 = (const float*)&pf[0];
                const float* p1 = (const float*)&pf[1];
                const float* p2 = (const float*)&pf[2];
                const float* p3 = (const float*)&pf[3];
                #pragma unroll
                for (int c = 0; c < 4; c++) {
                    int k = (e_id & 3) * 4 + c;
                    float* d = sm + rowX(e_id >> 2) + cslot(k) * 16 + t0;
                    *(float4*)d = make_float4(p0[c], p1[c], p2[c], p3[c]);
                }
                if (tid < TPG) rw[tid] = prw;
            }
        }
    }
}

extern "C" void kernel_launch(void* const* d_in, const int* in_sizes, int n_in,
                              void* d_out, int out_size)
{
    const float* x     = (const float*)d_in[0];
    const float* ref   = (const float*)d_in[1];
    const float* w_bil = (const float*)d_in[2];
    const float* b_bil = (const float*)d_in[3];
    const float* w_out = (const float*)d_in[4];
    const float* b_out = (const float*)d_in[5];
    float* out = (float*)d_out;

    int ntok    = in_sizes[0] / 512;   // 32 channels * 16 components
    int ngroups = ntok / TPG;

    cudaFuncSetAttribute(gatr_fused_kernel,
                         cudaFuncAttributeMaxDynamicSharedMemorySize, SMEM_BYTES);
    gatr_fused_kernel<<<152, NTHR, SMEM_BYTES>>>(x, ref, w_bil, b_bil, w_out, b_out,
                                                 out, ngroups);
}

// round 12
// speedup vs baseline: 1.1078x; 1.1078x over previous
#include <cuda_runtime.h>

#define NTHR 512
#define TPG  16            // tokens per group
#define S    276           // staging row stride in floats (16*16 + 20 pad)

typedef unsigned long long ull;

// ---------------- shared memory layout (in floats) ----------------
#define WBT_SZ  (9*32*64)              // wbT[a][i][o], o contiguous
#define WOT_SZ  (9*32*32)              // woT[a][i][o]
#define XS_SZ   (32*S + 8)             // xs rows (aliased by gs in P3/P4)
#define HS_SZ   (64*S + 8)             // hs rows (aliased by out-staging)
#define WBT_OFF 0
#define WOT_OFF (WBT_OFF + WBT_SZ)
#define XS_OFF  (WOT_OFF + WOT_SZ)
#define HS_OFF  (XS_OFF + XS_SZ)
#define BB_OFF  (HS_OFF + HS_SZ)       // 64
#define BO_OFF  (BB_OFF + 64)          // 32
#define RW_OFF  (BO_OFF + 32)          // 16
#define F_TOTAL (RW_OFF + 16)
#define SMEM_BYTES (F_TOTAL * 4)

// component slot swizzle (bijective), bank-swizzled row offsets
__host__ __device__ constexpr int cslot(int k) { return k ^ (k >> 2); }
__host__ __device__ constexpr int rowX(int i)  { return XS_OFF + i * S + ((i >> 3) & 1) * 4; }
__host__ __device__ constexpr int rowH(int o)  { return HS_OFF + o * S + ((o >> 3) & 1) * 4; }

// ---------------- blade algebra ----------------
// blade order: 1,e0,e1,e2,e3,e01,e02,e03,e12,e13,e23,e012,e013,e023,e123,e0123
__constant__ int c_GRADE[16] = {0,1,1,1,1,2,2,2,2,2,2,3,3,3,3,4};
__constant__ int c_PART [16] = {-1,0,-1,-1,-1,2,3,4,-1,-1,-1,8,9,10,-1,14};
__constant__ int c_A2   [16] = {0,5,0,0,0,6,6,6,0,0,0,7,7,7,0,8};
// warp -> component; EK/NK interleaved in groups of 4 so each SMSP gets 2+2
__constant__ int c_KORD [16] = {1,5,6,7, 0,2,3,4, 11,12,13,15, 8,9,10,14};

// ---- compile-time Cayley tables ----
constexpr int MASKC[16]  = {0,1,2,4,8,3,5,9,6,10,12,7,11,13,14,15};
constexpr int IMASKC[16] = {0,1,2,5,3,6,8,11,4,7,9,12,10,13,14,15};
constexpr int popc4c(int x) { int v = 0; for (int b = 0; b < 4; b++) v += (x >> b) & 1; return v; }
constexpr int invcc(int A, int B) {
    int v = 0;
    for (int g = 0; g < 4; g++) if ((B >> g) & 1) v += popc4c(A >> (g + 1));
    return v;
}
struct CTerm { int i, j, s; };
struct CK    { CTerm t[16]; int n; };
struct CTabs { CK gp[16]; CK jc[16]; };
constexpr CTabs buildT() {
    CTabs T{};
    for (int i = 0; i < 16; i++)
        for (int j = 0; j < 16; j++) {
            int A = MASKC[i], B = MASKC[j];
            if (A & B & 1) continue;                    // e0*e0 = 0
            int s = (invcc(A, B) & 1) ? -1 : 1;
            int k = IMASKC[A ^ B];
            T.gp[k].t[T.gp[k].n].i = i;
            T.gp[k].t[T.gp[k].n].j = j;
            T.gp[k].t[T.gp[k].n].s = s;
            T.gp[k].n++;
        }
    int ds[16] = {};
    for (int i = 0; i < 16; i++) {
        int A = MASKC[i];
        ds[i] = (invcc(A, 15 ^ A) & 1) ? -1 : 1;
    }
    for (int i = 0; i < 16; i++)
        for (int j = 0; j < 16; j++) {
            int A = MASKC[i], B = MASKC[j];
            int da = 15 ^ A, db = 15 ^ B;
            if (da & db) continue;                      // wedge of duals vanishes
            int w  = (invcc(da, db) & 1) ? -1 : 1;
            int kk = IMASKC[A & B];
            int val = ds[i] * ds[j] * w * ds[kk];
            T.jc[kk].t[T.jc[kk].n].i = i;
            T.jc[kk].t[T.jc[kk].n].j = j;
            T.jc[kk].t[T.jc[kk].n].s = val;
            T.jc[kk].n++;
        }
    return T;
}
constexpr CTabs CT = buildT();

// ---- packed f32x2 helpers ----
__device__ __forceinline__ void fma2(ull& d, ull a, ull b) {
    asm("fma.rn.f32x2 %0, %1, %2, %0;" : "+l"(d) : "l"(a), "l"(b));
}
__device__ __forceinline__ ull pk2(float s) {
    ull d; asm("mov.b64 %0, {%1, %1};" : "=l"(d) : "f"(s)); return d;
}
__device__ __forceinline__ void add2(ull& d, ull a) {
    asm("add.rn.f32x2 %0, %0, %1;" : "+l"(d) : "l"(a));
}

// ---- MAC block: 32 i-iters, o-quad (float4 weight) x NP packed tokens ----
template<int NP>
__device__ __forceinline__ void mac32_q(
    ull (&acc)[4][NP], const float* __restrict__ w, int ws,
    const float* __restrict__ smb, int sl)
{
    #pragma unroll 8
    for (int i = 0; i < 32; i++) {
        float4 wv = *(const float4*)(w + i * ws);
        const float* xp = smb + rowX(i) + sl;
        ull xv[NP];
        if constexpr (NP == 4) {
            ulonglong2 u0 = *(const ulonglong2*)(xp);
            ulonglong2 u1 = *(const ulonglong2*)(xp + 4);
            xv[0] = u0.x; xv[1] = u0.y; xv[2] = u1.x; xv[3] = u1.y;
        } else {
            ulonglong2 u0 = *(const ulonglong2*)(xp);
            xv[0] = u0.x; xv[1] = u0.y;
        }
        ull w0 = pk2(wv.x), w1 = pk2(wv.y), w2 = pk2(wv.z), w3 = pk2(wv.w);
        #pragma unroll
        for (int p = 0; p < NP; p++) {
            fma2(acc[0][p], xv[p], w0); fma2(acc[1][p], xv[p], w1);
            fma2(acc[2][p], xv[p], w2); fma2(acc[3][p], xv[p], w3);
        }
    }
}

// ---- P3: one component K, compile-time term list ----
template<int SIDE, int K>
__device__ __forceinline__ float bil_k(const float (&L)[16], const float (&R)[16]) {
    constexpr CK ck = SIDE ? CT.jc[K] : CT.gp[K];
    float acc = 0.f;
    #pragma unroll
    for (int e = 0; e < ck.n; e++) {
        float l = (ck.t[e].s < 0) ? -L[ck.t[e].i] : L[ck.t[e].i];
        acc = fmaf(l, R[ck.t[e].j], acc);
    }
    return acc;
}

template<int SIDE, int K>
__device__ __forceinline__ void bil_all(const float (&L)[16], const float (&R)[16],
                                        float* __restrict__ dst, float scale) {
    if constexpr (K < 16) {
        float v = bil_k<SIDE, K>(L, R);
        if constexpr (SIDE) v *= scale;
        dst[cslot(K) * 16] = v;
        bil_all<SIDE, K + 1>(L, R, dst, scale);
    }
}

__global__ __launch_bounds__(NTHR, 1)
void gatr_fused_kernel(
    const float* __restrict__ x, const float* __restrict__ ref,
    const float* __restrict__ w_bil, const float* __restrict__ b_bil,
    const float* __restrict__ w_out, const float* __restrict__ b_out,
    float* __restrict__ out, int ngroups)
{
    extern __shared__ float sm[];
    float* wbT = sm + WBT_OFF;
    float* woT = sm + WOT_OFF;
    float* bb  = sm + BB_OFF;
    float* bo  = sm + BO_OFF;
    float* rw  = sm + RW_OFF;

    const int tid = threadIdx.x;

    // ---- stage weights transposed ----
    for (int e = tid; e < 64 * 32 * 9; e += NTHR) {
        int o = e / 288, r = e % 288, i = r / 9, a = r % 9;
        wbT[(a * 32 + i) * 64 + o] = w_bil[e];
    }
    for (int e = tid; e < 32 * 32 * 9; e += NTHR) {
        int o = e / 288, r = e % 288, i = r / 9, a = r % 9;
        woT[(a * 32 + i) * 32 + o] = w_out[e];
    }
    if (tid < 64) bb[tid] = b_bil[tid];
    if (tid < 32) bo[tid] = b_out[tid];

    const int e_id = tid & 127;
    const int t0   = (tid >> 7) * 4;

    // ---- prefetch + stage first group ----
    float4 pf[4];
    float  prw = 0.f;
    {
        int g = blockIdx.x;
        size_t base = ((size_t)g * TPG + t0) * 512 + (size_t)e_id * 4;
        #pragma unroll
        for (int j = 0; j < 4; j++) pf[j] = *(const float4*)(x + base + (size_t)j * 512);
        if (tid < TPG) prw = ref[((size_t)g * TPG + tid) * 16 + 15];

        const float* p0 = (const float*)&pf[0];
        const float* p1 = (const float*)&pf[1];
        const float* p2 = (const float*)&pf[2];
        const float* p3 = (const float*)&pf[3];
        #pragma unroll
        for (int c = 0; c < 4; c++) {
            int k = (e_id & 3) * 4 + c;
            float* d = sm + rowX(e_id >> 2) + cslot(k) * 16 + t0;
            *(float4*)d = make_float4(p0[c], p1[c], p2[c], p3[c]);
        }
        if (tid < TPG) rw[tid] = prw;
    }

    const int w_id = tid >> 5, lane = tid & 31;
    const int k_my = c_KORD[w_id];

    for (int g = blockIdx.x; g < ngroups; g += gridDim.x) {
        __syncthreads();   // xs / rw ready

        // prefetch next group (LDG latency hidden under P2)
        int gn = g + gridDim.x;
        bool more = gn < ngroups;
        if (more) {
            size_t base = ((size_t)gn * TPG + t0) * 512 + (size_t)e_id * 4;
            #pragma unroll
            for (int j = 0; j < 4; j++) pf[j] = *(const float4*)(x + base + (size_t)j * 512);
            if (tid < TPG) prw = ref[((size_t)gn * TPG + tid) * 16 + 15];
        }

        // ---- P2: equi_linear #1 -> hs rows 0..63 ----
        // warp = one component; lane = token-half(2) x o-quad(16): 4 o x 8 tok
        {
            const int h = lane >> 4, q = lane & 15;
            const int k = k_my, o0 = 4 * q;
            const int sl = cslot(k) * 16 + h * 8;
            ull acc[4][4];
            #pragma unroll
            for (int oo = 0; oo < 4; oo++)
                #pragma unroll
                for (int p = 0; p < 4; p++) acc[oo][p] = 0ull;

            mac32_q<4>(acc, wbT + (c_GRADE[k] * 32) * 64 + o0, 64, sm, sl);
            int pk = c_PART[k];
            if (pk >= 0)
                mac32_q<4>(acc, wbT + (c_A2[k] * 32) * 64 + o0, 64, sm,
                           cslot(pk) * 16 + h * 8);

            if (k == 0) {
                #pragma unroll
                for (int oo = 0; oo < 4; oo++) {
                    ull b = pk2(bb[o0 + oo]);
                    #pragma unroll
                    for (int p = 0; p < 4; p++) add2(acc[oo][p], b);
                }
            }
            #pragma unroll
            for (int oo = 0; oo < 4; oo++) {
                float* d = sm + rowH(o0 + oo) + sl;
                *(ulonglong2*)(d)     = make_ulonglong2(acc[oo][0], acc[oo][1]);
                *(ulonglong2*)(d + 4) = make_ulonglong2(acc[oo][2], acc[oo][3]);
            }
        }
        __syncthreads();

        // ---- P3: GP + join -> gs (xs region) rows 0..31 (512 threads) ----
        {
            int side = tid >> 8, c = (tid >> 4) & 15, t = tid & 15;
            const float* Lp = sm + rowH(side * 32 + c) + t;
            const float* Rp = sm + rowH(side * 32 + 16 + c) + t;
            float L[16], R[16];
            #pragma unroll
            for (int i = 0; i < 16; i++) {
                L[i] = Lp[cslot(i) * 16];
                R[i] = Rp[cslot(i) * 16];
            }
            float* dst = sm + rowX(side * 16 + c) + t;
            float scale = rw[t];
            if (side == 0) bil_all<0, 0>(L, R, dst, scale);
            else           bil_all<1, 0>(L, R, dst, scale);
        }
        __syncthreads();

        // ---- P4: equi_linear #2 -> staging in hs rows 0..31 ----
        // warp = one component; lane = token-quarter(4) x o-quad(8): 4 o x 4 tok
        {
            const int h = lane >> 3, q = lane & 7;
            const int k = k_my, o0 = 4 * q;
            const int sl = cslot(k) * 16 + h * 4;
            ull acc[4][2];
            #pragma unroll
            for (int oo = 0; oo < 4; oo++) { acc[oo][0] = 0ull; acc[oo][1] = 0ull; }

            mac32_q<2>(acc, woT + (c_GRADE[k] * 32) * 32 + o0, 32, sm, sl);
            int pk = c_PART[k];
            if (pk >= 0)
                mac32_q<2>(acc, woT + (c_A2[k] * 32) * 32 + o0, 32, sm,
                           cslot(pk) * 16 + h * 4);

            if (k == 0) {
                #pragma unroll
                for (int oo = 0; oo < 4; oo++) {
                    ull b = pk2(bo[o0 + oo]);
                    add2(acc[oo][0], b); add2(acc[oo][1], b);
                }
            }
            #pragma unroll
            for (int oo = 0; oo < 4; oo++) {
                float* d = sm + rowH(o0 + oo) + sl;
                *(ulonglong2*)(d) = make_ulonglong2(acc[oo][0], acc[oo][1]);
            }
        }
        __syncthreads();

        // ---- P5: coalesced store + stage next group's x ----
        {
            float4 sv[4];
            #pragma unroll
            for (int c = 0; c < 4; c++) {
                int k = (e_id & 3) * 4 + c;
                sv[c] = *(const float4*)(sm + rowH(e_id >> 2) + cslot(k) * 16 + t0);
            }
            size_t base = ((size_t)g * TPG + t0) * 512 + (size_t)e_id * 4;
            const float* s0 = (const float*)&sv[0];
            const float* s1 = (const float*)&sv[1];
            const float* s2 = (const float*)&sv[2];
            const float* s3 = (const float*)&sv[3];
            #pragma unroll
            for (int j = 0; j < 4; j++)
                *(float4*)(out + base + (size_t)j * 512) =
                    make_float4(s0[j], s1[j], s2[j], s3[j]);

            if (more) {
                const float* p0 = (const float*)&pf[0];
                const float* p1 = (const float*)&pf[1];
                const float* p2 = (const float*)&pf[2];
                const float* p3 = (const float*)&pf[3];
                #pragma unroll
                for (int c = 0; c < 4; c++) {
                    int k = (e_id & 3) * 4 + c;
                    float* d = sm + rowX(e_id >> 2) + cslot(k) * 16 + t0;
                    *(float4*)d = make_float4(p0[c], p1[c], p2[c], p3[c]);
                }
                if (tid < TPG) rw[tid] = prw;
            }
        }
    }
}

extern "C" void kernel_launch(void* const* d_in, const int* in_sizes, int n_in,
                              void* d_out, int out_size)
{
    const float* x     = (const float*)d_in[0];
    const float* ref   = (const float*)d_in[1];
    const float* w_bil = (const float*)d_in[2];
    const float* b_bil = (const float*)d_in[3];
    const float* w_out = (const float*)d_in[4];
    const float* b_out = (const float*)d_in[5];
    float* out = (float*)d_out;

    int ntok    = in_sizes[0] / 512;   // 32 channels * 16 components
    int ngroups = ntok / TPG;

    cudaFuncSetAttribute(gatr_fused_kernel,
                         cudaFuncAttributeMaxDynamicSharedMemorySize, SMEM_BYTES);
    gatr_fused_kernel<<<152, NTHR, SMEM_BYTES>>>(x, ref, w_bil, b_bil, w_out, b_out,
                                                 out, ngroups);
}